// round 1
// baseline (speedup 1.0000x reference)
#include <cuda_runtime.h>

#define B_   2
#define N_   169
#define NN_  338
#define C_   256
#define H_   4
#define HC_  1024
#define L_   3

// ---------------- scratch (device globals; no allocation allowed) ----------
__device__ float g_x[NN_ * C_];        // running node features
__device__ float g_xl[NN_ * HC_];      // x @ Wl + bl
__device__ float g_xr[NN_ * HC_];      // x @ Wr + br
__device__ float g_logits[B_ * H_ * N_ * N_];  // logits, then alpha in-place
__device__ float g_hpre[NN_ * C_];     // head-mean agg + bias
__device__ float g_h[NN_ * C_];        // post layernorm
__device__ float g_m[NN_ * 2 * C_];    // mlp hidden

// ---------------- generic 32x32 tiled fp32 GEMM ---------------------------
// out = A[M,K] @ Bm[K,N] (+bias). mode: 0 plain, 1 relu, 2 residual +=
__global__ void gemm_kernel(const float* __restrict__ A,
                            const float* __restrict__ Bm,
                            const float* __restrict__ bias,
                            float* __restrict__ out,
                            int M, int N, int K, int mode)
{
    __shared__ float As[32][33];
    __shared__ float Bs[32][33];
    int tid = threadIdx.x;
    int tx = tid & 15, ty = tid >> 4;
    int m0 = blockIdx.y * 32;
    int n0 = blockIdx.x * 32;
    float a00 = 0.f, a01 = 0.f, a10 = 0.f, a11 = 0.f;

    for (int kk = 0; kk < K; kk += 32) {
#pragma unroll
        for (int i = 0; i < 4; i++) {
            int ii = tid + i * 256;
            int r = ii >> 5, c = ii & 31;
            int arow = m0 + r;
            As[r][c] = (arow < M) ? A[arow * K + kk + c] : 0.f;
            Bs[r][c] = Bm[(kk + r) * N + n0 + c];
        }
        __syncthreads();
#pragma unroll
        for (int k = 0; k < 32; k++) {
            float av0 = As[ty][k],      av1 = As[ty + 16][k];
            float bv0 = Bs[k][tx],      bv1 = Bs[k][tx + 16];
            a00 = fmaf(av0, bv0, a00);  a01 = fmaf(av0, bv1, a01);
            a10 = fmaf(av1, bv0, a10);  a11 = fmaf(av1, bv1, a11);
        }
        __syncthreads();
    }

    int r0 = m0 + ty, r1 = m0 + ty + 16;
    int c0 = n0 + tx, c1 = n0 + tx + 16;
    float b0 = bias[c0], b1 = bias[c1];
    if (mode == 0) {
        if (r0 < M) { out[r0 * N + c0] = a00 + b0; out[r0 * N + c1] = a01 + b1; }
        if (r1 < M) { out[r1 * N + c0] = a10 + b0; out[r1 * N + c1] = a11 + b1; }
    } else if (mode == 1) {
        if (r0 < M) { out[r0 * N + c0] = fmaxf(a00 + b0, 0.f); out[r0 * N + c1] = fmaxf(a01 + b1, 0.f); }
        if (r1 < M) { out[r1 * N + c0] = fmaxf(a10 + b0, 0.f); out[r1 * N + c1] = fmaxf(a11 + b1, 0.f); }
    } else {
        if (r0 < M) { out[r0 * N + c0] += a00 + b0; out[r0 * N + c1] += a01 + b1; }
        if (r1 < M) { out[r1 * N + c0] += a10 + b0; out[r1 * N + c1] += a11 + b1; }
    }
}

// ---------------- dense GATv2 logits: logits[b,h,d,s] ----------------------
// logit = sum_c leakyrelu(xl[s,h,c] + xr[d,h,c], 0.2) * att[h,c]
__global__ void logits_kernel(const float* __restrict__ xl,
                              const float* __restrict__ xr,
                              const float* __restrict__ att_l,
                              float* __restrict__ logits)
{
    __shared__ float XL[32][33];
    __shared__ float XR[32][33];
    __shared__ float AT[32];
    int tid = threadIdx.x;
    int tx = tid & 15, ty = tid >> 4;
    int bh = blockIdx.z;
    int b = bh >> 2, h = bh & 3;
    int d0 = blockIdx.y * 32;
    int s0 = blockIdx.x * 32;

    float a00 = 0.f, a01 = 0.f, a10 = 0.f, a11 = 0.f; // [d][s]

    for (int ck = 0; ck < C_; ck += 32) {
#pragma unroll
        for (int i = 0; i < 4; i++) {
            int ii = tid + i * 256;
            int r = ii >> 5, c = ii & 31;
            int sn = s0 + r, dn = d0 + r;
            XL[r][c] = (sn < N_) ? xl[(b * N_ + sn) * HC_ + h * C_ + ck + c] : 0.f;
            XR[r][c] = (dn < N_) ? xr[(b * N_ + dn) * HC_ + h * C_ + ck + c] : 0.f;
        }
        if (tid < 32) AT[tid] = att_l[h * C_ + ck + tid];
        __syncthreads();
#pragma unroll
        for (int c = 0; c < 32; c++) {
            float av = AT[c];
            float l0 = XL[tx][c],      l1 = XL[tx + 16][c];
            float r0 = XR[ty][c],      r1 = XR[ty + 16][c];
            float s;
            s = l0 + r0; a00 = fmaf(fmaf(0.2f, fminf(s, 0.f), fmaxf(s, 0.f)), av, a00);
            s = l1 + r0; a01 = fmaf(fmaf(0.2f, fminf(s, 0.f), fmaxf(s, 0.f)), av, a01);
            s = l0 + r1; a10 = fmaf(fmaf(0.2f, fminf(s, 0.f), fmaxf(s, 0.f)), av, a10);
            s = l1 + r1; a11 = fmaf(fmaf(0.2f, fminf(s, 0.f), fmaxf(s, 0.f)), av, a11);
        }
        __syncthreads();
    }

    int dd0 = d0 + ty, dd1 = d0 + ty + 16;
    int ss0 = s0 + tx, ss1 = s0 + tx + 16;
    float* base = logits + (size_t)bh * N_ * N_;
    if (dd0 < N_) {
        if (ss0 < N_) base[dd0 * N_ + ss0] = (dd0 == ss0) ? -1e30f : a00;
        if (ss1 < N_) base[dd0 * N_ + ss1] = (dd0 == ss1) ? -1e30f : a01;
    }
    if (dd1 < N_) {
        if (ss0 < N_) base[dd1 * N_ + ss0] = (dd1 == ss0) ? -1e30f : a10;
        if (ss1 < N_) base[dd1 * N_ + ss1] = (dd1 == ss1) ? -1e30f : a11;
    }
}

// ---------------- softmax over src per (b,h,dst) row, in-place -------------
__global__ void softmax_kernel(float* __restrict__ logits)
{
    int w = threadIdx.x >> 5, lane = threadIdx.x & 31;
    int row = blockIdx.x * 8 + w;               // 169 blocks * 8 warps = 1352 rows
    float* p = logits + (size_t)row * N_;
    float v[6];
    float mx = -1e30f;
#pragma unroll
    for (int i = 0; i < 6; i++) {
        int s = lane + i * 32;
        v[i] = (s < N_) ? p[s] : -1e30f;
        mx = fmaxf(mx, v[i]);
    }
#pragma unroll
    for (int o = 16; o; o >>= 1) mx = fmaxf(mx, __shfl_xor_sync(0xffffffffu, mx, o));
    float sum = 0.f;
#pragma unroll
    for (int i = 0; i < 6; i++) {
        float e = __expf(v[i] - mx);
        v[i] = e;
        sum += e;
    }
#pragma unroll
    for (int o = 16; o; o >>= 1) sum += __shfl_xor_sync(0xffffffffu, sum, o);
    float inv = 1.f / (sum + 1e-16f);
#pragma unroll
    for (int i = 0; i < 6; i++) {
        int s = lane + i * 32;
        if (s < N_) p[s] = v[i] * inv;
    }
}

// ---------------- aggregation: out[d,c] = mean_h sum_s alpha*xl + bias ------
__global__ void agg_kernel(const float* __restrict__ alpha,
                           const float* __restrict__ xl,
                           const float* __restrict__ bias_l,
                           float* __restrict__ out)
{
    __shared__ float Al[32][33];
    __shared__ float Xs[32][33];
    int tid = threadIdx.x;
    int tx = tid & 15, ty = tid >> 4;
    int b = blockIdx.z;
    int d0 = blockIdx.y * 32;
    int c0 = blockIdx.x * 32;
    float a00 = 0.f, a01 = 0.f, a10 = 0.f, a11 = 0.f;

    for (int h = 0; h < H_; h++) {
        const float* arow = alpha + (size_t)((b * H_ + h) * N_) * N_;
        for (int sk = 0; sk < N_; sk += 32) {
#pragma unroll
            for (int i = 0; i < 4; i++) {
                int ii = tid + i * 256;
                int r = ii >> 5, c = ii & 31;
                int d = d0 + r, s = sk + c;
                Al[r][c] = (d < N_ && s < N_) ? arow[d * N_ + s] : 0.f;
                int sn = sk + r;
                Xs[r][c] = (sn < N_) ? xl[(b * N_ + sn) * HC_ + h * C_ + c0 + c] : 0.f;
            }
            __syncthreads();
#pragma unroll
            for (int k = 0; k < 32; k++) {
                float p0 = Al[ty][k],      p1 = Al[ty + 16][k];
                float q0 = Xs[k][tx],      q1 = Xs[k][tx + 16];
                a00 = fmaf(p0, q0, a00);   a01 = fmaf(p0, q1, a01);
                a10 = fmaf(p1, q0, a10);   a11 = fmaf(p1, q1, a11);
            }
            __syncthreads();
        }
    }

    int dd0 = d0 + ty, dd1 = d0 + ty + 16;
    int cc0 = c0 + tx, cc1 = c0 + tx + 16;
    float b0 = bias_l[cc0], b1 = bias_l[cc1];
    if (dd0 < N_) {
        out[(b * N_ + dd0) * C_ + cc0] = 0.25f * a00 + b0;
        out[(b * N_ + dd0) * C_ + cc1] = 0.25f * a01 + b1;
    }
    if (dd1 < N_) {
        out[(b * N_ + dd1) * C_ + cc0] = 0.25f * a10 + b0;
        out[(b * N_ + dd1) * C_ + cc1] = 0.25f * a11 + b1;
    }
}

// ---------------- layernorm over C=256 per node -----------------------------
__global__ void ln_kernel(const float* __restrict__ in,
                          const float* __restrict__ g,
                          const float* __restrict__ bt,
                          float* __restrict__ out)
{
    int row = blockIdx.x, t = threadIdx.x;
    int lane = t & 31, w = t >> 5;
    float v = in[row * C_ + t];

    __shared__ float red[8];
    __shared__ float stat;

    float s = v;
#pragma unroll
    for (int o = 16; o; o >>= 1) s += __shfl_xor_sync(0xffffffffu, s, o);
    if (lane == 0) red[w] = s;
    __syncthreads();
    if (t == 0) {
        float tot = 0.f;
#pragma unroll
        for (int i = 0; i < 8; i++) tot += red[i];
        stat = tot * (1.f / C_);
    }
    __syncthreads();
    float mu = stat;
    float d = v - mu;
    float s2 = d * d;
#pragma unroll
    for (int o = 16; o; o >>= 1) s2 += __shfl_xor_sync(0xffffffffu, s2, o);
    __syncthreads();
    if (lane == 0) red[w] = s2;
    __syncthreads();
    if (t == 0) {
        float tot = 0.f;
#pragma unroll
        for (int i = 0; i < 8; i++) tot += red[i];
        stat = rsqrtf(tot * (1.f / C_) + 1e-5f);
    }
    __syncthreads();
    out[row * C_ + t] = d * stat * g[t] + bt[t];
}

// ---------------- final mean pool per graph ---------------------------------
__global__ void pool_kernel(const float* __restrict__ x, float* __restrict__ out)
{
    int b = blockIdx.x, t = threadIdx.x;
    float s = 0.f;
#pragma unroll 13
    for (int d = 0; d < N_; d++) s += x[(b * N_ + d) * C_ + t];
    out[b * C_ + t] = s * (1.f / N_);
}

__global__ void copy_kernel(const float* __restrict__ src, float* __restrict__ dst)
{
    int i = blockIdx.x * 256 + threadIdx.x;
    dst[i] = src[i];
}

// ---------------- host launcher ---------------------------------------------
extern "C" void kernel_launch(void* const* d_in, const int* in_sizes, int n_in,
                              void* d_out, int out_size)
{
    const float* x   = (const float*)d_in[0];
    const float* Wl  = (const float*)d_in[1];
    const float* bl  = (const float*)d_in[2];
    const float* Wr  = (const float*)d_in[3];
    const float* br  = (const float*)d_in[4];
    const float* att = (const float*)d_in[5];
    const float* bias= (const float*)d_in[6];
    const float* lng = (const float*)d_in[7];
    const float* lnb = (const float*)d_in[8];
    const float* W1  = (const float*)d_in[9];
    const float* b1  = (const float*)d_in[10];
    const float* W2  = (const float*)d_in[11];
    const float* b2  = (const float*)d_in[12];
    // d_in[13..15]: edge_src, edge_dst, batch_ids — structure is dense; unused.

    float *bx, *bxl, *bxr, *blg, *bhp, *bh, *bm;
    cudaGetSymbolAddress((void**)&bx,  g_x);
    cudaGetSymbolAddress((void**)&bxl, g_xl);
    cudaGetSymbolAddress((void**)&bxr, g_xr);
    cudaGetSymbolAddress((void**)&blg, g_logits);
    cudaGetSymbolAddress((void**)&bhp, g_hpre);
    cudaGetSymbolAddress((void**)&bh,  g_h);
    cudaGetSymbolAddress((void**)&bm,  g_m);

    copy_kernel<<<NN_, 256>>>(x, bx);

    for (int l = 0; l < L_; l++) {
        gemm_kernel<<<dim3(HC_ / 32, 11), 256>>>(bx, Wl + l * C_ * HC_, bl + l * HC_,
                                                 bxl, NN_, HC_, C_, 0);
        gemm_kernel<<<dim3(HC_ / 32, 11), 256>>>(bx, Wr + l * C_ * HC_, br + l * HC_,
                                                 bxr, NN_, HC_, C_, 0);
        logits_kernel<<<dim3(6, 6, B_ * H_), 256>>>(bxl, bxr, att + l * H_ * C_, blg);
        softmax_kernel<<<169, 256>>>(blg);
        agg_kernel<<<dim3(C_ / 32, 6, B_), 256>>>(blg, bxl, bias + l * C_, bhp);
        ln_kernel<<<NN_, 256>>>(bhp, lng + l * C_, lnb + l * C_, bh);
        gemm_kernel<<<dim3(2 * C_ / 32, 11), 256>>>(bh, W1 + l * C_ * 2 * C_, b1 + l * 2 * C_,
                                                    bm, NN_, 2 * C_, C_, 1);
        gemm_kernel<<<dim3(C_ / 32, 11), 256>>>(bm, W2 + l * 2 * C_ * C_, b2 + l * C_,
                                                bx, NN_, C_, 2 * C_, 2);
    }

    pool_kernel<<<B_, 256>>>(bx, (float*)d_out);
}

// round 2
// speedup vs baseline: 1.0997x; 1.0997x over previous
#include <cuda_runtime.h>

#define B_   2
#define N_   169
#define NN_  338
#define C_   256
#define H_   4
#define HC_  1024
#define L_   3

// ---------------- scratch (device globals) ---------------------------------
__device__ float g_x[NN_ * C_];               // running node features
__device__ float g_xl[NN_ * HC_];             // x @ Wl + bl
__device__ float g_xr[NN_ * HC_];             // x @ Wr + br
__device__ float g_alpha[B_ * H_ * N_ * N_];  // attention weights
__device__ float g_hpre[NN_ * C_];            // head-mean agg + bias
__device__ float g_h[NN_ * C_];               // post layernorm
__device__ float g_m[NN_ * 2 * C_];           // mlp hidden

// ---------------- packed f32x2 MAC for leaky-relu attention ----------------
__device__ __forceinline__ void mac2(unsigned long long l, unsigned long long r,
                                     unsigned long long a6, unsigned long long a4,
                                     unsigned long long msk, unsigned long long& acc)
{
    unsigned long long s, m;
    asm("add.rn.f32x2 %0, %1, %2;" : "=l"(s) : "l"(l), "l"(r));
    asm("and.b64 %0, %1, %2;"      : "=l"(m) : "l"(s), "l"(msk));
    asm("fma.rn.f32x2 %0, %1, %2, %0;" : "+l"(acc) : "l"(s), "l"(a6));
    asm("fma.rn.f32x2 %0, %1, %2, %0;" : "+l"(acc) : "l"(m), "l"(a4));
}

// ---------------- fused logits + softmax ------------------------------------
// grid (11 d-tiles, 8 bh). Each block: 16 d rows x all 169 s.
// logit(d,s) = sum_c lrelu(xl[s,c]+xr[d,c]) * att[c] ; then row softmax.
__global__ __launch_bounds__(256) void attn_kernel(const float* __restrict__ xl,
                                                   const float* __restrict__ xr,
                                                   const float* __restrict__ att_l,
                                                   float* __restrict__ alpha)
{
    __shared__ __align__(16) float XR[16][38];
    __shared__ __align__(16) float XLs[6][32][38];
    __shared__ __align__(16) float A6[32];
    __shared__ __align__(16) float A4[32];

    int tid = threadIdx.x;
    int tx = tid & 15, ty = tid >> 4;
    int dt = blockIdx.x, bh = blockIdx.y;
    int b = bh >> 2, h = bh & 3;
    int d = dt * 16 + ty;
    bool dok = d < N_;

    unsigned long long acc[6][2];
#pragma unroll
    for (int st = 0; st < 6; st++) { acc[st][0] = 0ull; acc[st][1] = 0ull; }
    const unsigned long long msk = 0x7FFFFFFF7FFFFFFFULL;

    for (int ck = 0; ck < C_; ck += 32) {
        {
            float2 v = make_float2(0.f, 0.f);
            if (dok) v = *(const float2*)&xr[(size_t)(b * N_ + d) * HC_ + h * C_ + ck + tx * 2];
            *(float2*)&XR[ty][tx * 2] = v;
        }
        if (tid < 32) {
            float a = att_l[h * C_ + ck + tid];
            A6[tid] = 0.6f * a;
            A4[tid] = 0.4f * a;
        }
#pragma unroll
        for (int st = 0; st < 6; st++) {
#pragma unroll
            for (int i = 0; i < 2; i++) {
                int f = tid + 256 * i;
                int row = f >> 4, cc = (f & 15) * 2;
                int s = st * 32 + row;
                float2 v = make_float2(0.f, 0.f);
                if (s < N_) v = *(const float2*)&xl[(size_t)(b * N_ + s) * HC_ + h * C_ + ck + cc];
                *(float2*)&XLs[st][row][cc] = v;
            }
        }
        __syncthreads();
#pragma unroll
        for (int c2 = 0; c2 < 16; c2++) {
            unsigned long long r  = *(const unsigned long long*)&XR[ty][c2 * 2];
            unsigned long long a6 = *(const unsigned long long*)&A6[c2 * 2];
            unsigned long long a4 = *(const unsigned long long*)&A4[c2 * 2];
#pragma unroll
            for (int st = 0; st < 6; st++) {
                unsigned long long l0 = *(const unsigned long long*)&XLs[st][tx][c2 * 2];
                unsigned long long l1 = *(const unsigned long long*)&XLs[st][tx + 16][c2 * 2];
                mac2(l0, r, a6, a4, msk, acc[st][0]);
                mac2(l1, r, a6, a4, msk, acc[st][1]);
            }
        }
        __syncthreads();
    }

    // fold packed halves, mask, softmax across the 16-lane group (one d/row)
    float lg[6][2];
    float mx = -1e30f;
#pragma unroll
    for (int st = 0; st < 6; st++)
#pragma unroll
        for (int j = 0; j < 2; j++) {
            unsigned long long a = acc[st][j];
            float lo = __uint_as_float((unsigned)(a & 0xffffffffu));
            float hi = __uint_as_float((unsigned)(a >> 32));
            float v = lo + hi;
            int s = st * 32 + tx + j * 16;
            if (s >= N_ || s == d) v = -1e30f;
            lg[st][j] = v;
            mx = fmaxf(mx, v);
        }
#pragma unroll
    for (int o = 1; o < 16; o <<= 1) mx = fmaxf(mx, __shfl_xor_sync(0xffffffffu, mx, o));
    float sum = 0.f;
#pragma unroll
    for (int st = 0; st < 6; st++)
#pragma unroll
        for (int j = 0; j < 2; j++) {
            float e = __expf(lg[st][j] - mx);
            lg[st][j] = e;
            sum += e;
        }
#pragma unroll
    for (int o = 1; o < 16; o <<= 1) sum += __shfl_xor_sync(0xffffffffu, sum, o);
    float inv = 1.f / (sum + 1e-16f);

    if (dok) {
        float* base = alpha + (size_t)bh * N_ * N_ + (size_t)d * N_;
#pragma unroll
        for (int st = 0; st < 6; st++)
#pragma unroll
            for (int j = 0; j < 2; j++) {
                int s = st * 32 + tx + j * 16;
                if (s < N_) base[s] = lg[st][j] * inv;
            }
    }
}

// ---------------- fused xl/xr GEMM: 64x32 tile, 4x2 per thread --------------
// blockIdx.x < 32 -> Wl branch, else Wr. N fixed = HC_.
__global__ __launch_bounds__(256) void gemm_dual(const float* __restrict__ A,
                                                 const float* __restrict__ B1,
                                                 const float* __restrict__ c1,
                                                 float* __restrict__ o1,
                                                 const float* __restrict__ B2,
                                                 const float* __restrict__ c2p,
                                                 float* __restrict__ o2,
                                                 int M, int K)
{
    __shared__ __align__(16) float As[16][68];
    __shared__ __align__(16) float Bs[16][34];

    const float* Bm;
    const float* bias;
    float* out;
    int n0;
    if (blockIdx.x < 32) { Bm = B1; bias = c1;  out = o1; n0 = blockIdx.x * 32; }
    else                 { Bm = B2; bias = c2p; out = o2; n0 = (blockIdx.x - 32) * 32; }

    int tid = threadIdx.x;
    int tx = tid & 15, ty = tid >> 4;
    int m0 = blockIdx.y * 64;
    int lm = tid & 63, kq = tid >> 6;
    int bk = tid >> 4, bn = (tid & 15) * 2;

    float acc[4][2];
#pragma unroll
    for (int i = 0; i < 4; i++) { acc[i][0] = 0.f; acc[i][1] = 0.f; }

    for (int kk = 0; kk < K; kk += 16) {
        float4 f = make_float4(0.f, 0.f, 0.f, 0.f);
        if (m0 + lm < M) f = *(const float4*)&A[(size_t)(m0 + lm) * K + kk + kq * 4];
        As[kq * 4 + 0][lm] = f.x;
        As[kq * 4 + 1][lm] = f.y;
        As[kq * 4 + 2][lm] = f.z;
        As[kq * 4 + 3][lm] = f.w;
        *(float2*)&Bs[bk][bn] = *(const float2*)&Bm[(size_t)(kk + bk) * HC_ + n0 + bn];
        __syncthreads();
#pragma unroll
        for (int k = 0; k < 16; k++) {
            float4 a = *(const float4*)&As[k][ty * 4];
            float2 bv = *(const float2*)&Bs[k][tx * 2];
            acc[0][0] = fmaf(a.x, bv.x, acc[0][0]); acc[0][1] = fmaf(a.x, bv.y, acc[0][1]);
            acc[1][0] = fmaf(a.y, bv.x, acc[1][0]); acc[1][1] = fmaf(a.y, bv.y, acc[1][1]);
            acc[2][0] = fmaf(a.z, bv.x, acc[2][0]); acc[2][1] = fmaf(a.z, bv.y, acc[2][1]);
            acc[3][0] = fmaf(a.w, bv.x, acc[3][0]); acc[3][1] = fmaf(a.w, bv.y, acc[3][1]);
        }
        __syncthreads();
    }

    float b0 = bias[n0 + tx * 2], b1 = bias[n0 + tx * 2 + 1];
#pragma unroll
    for (int i = 0; i < 4; i++) {
        int r = m0 + ty * 4 + i;
        if (r < M) {
            out[(size_t)r * HC_ + n0 + tx * 2]     = acc[i][0] + b0;
            out[(size_t)r * HC_ + n0 + tx * 2 + 1] = acc[i][1] + b1;
        }
    }
}

// ---------------- generic 32x32 tiled fp32 GEMM (MLP path) ------------------
// mode: 0 plain, 1 relu, 2 residual +=
__global__ void gemm_kernel(const float* __restrict__ A,
                            const float* __restrict__ Bm,
                            const float* __restrict__ bias,
                            float* __restrict__ out,
                            int M, int N, int K, int mode)
{
    __shared__ float As[32][33];
    __shared__ float Bs[32][33];
    int tid = threadIdx.x;
    int tx = tid & 15, ty = tid >> 4;
    int m0 = blockIdx.y * 32;
    int n0 = blockIdx.x * 32;
    float a00 = 0.f, a01 = 0.f, a10 = 0.f, a11 = 0.f;

    for (int kk = 0; kk < K; kk += 32) {
#pragma unroll
        for (int i = 0; i < 4; i++) {
            int ii = tid + i * 256;
            int r = ii >> 5, c = ii & 31;
            int arow = m0 + r;
            As[r][c] = (arow < M) ? A[arow * K + kk + c] : 0.f;
            Bs[r][c] = Bm[(kk + r) * N + n0 + c];
        }
        __syncthreads();
#pragma unroll
        for (int k = 0; k < 32; k++) {
            float av0 = As[ty][k],      av1 = As[ty + 16][k];
            float bv0 = Bs[k][tx],      bv1 = Bs[k][tx + 16];
            a00 = fmaf(av0, bv0, a00);  a01 = fmaf(av0, bv1, a01);
            a10 = fmaf(av1, bv0, a10);  a11 = fmaf(av1, bv1, a11);
        }
        __syncthreads();
    }

    int r0 = m0 + ty, r1 = m0 + ty + 16;
    int c0 = n0 + tx, c1 = n0 + tx + 16;
    float b0 = bias[c0], b1 = bias[c1];
    if (mode == 0) {
        if (r0 < M) { out[r0 * N + c0] = a00 + b0; out[r0 * N + c1] = a01 + b1; }
        if (r1 < M) { out[r1 * N + c0] = a10 + b0; out[r1 * N + c1] = a11 + b1; }
    } else if (mode == 1) {
        if (r0 < M) { out[r0 * N + c0] = fmaxf(a00 + b0, 0.f); out[r0 * N + c1] = fmaxf(a01 + b1, 0.f); }
        if (r1 < M) { out[r1 * N + c0] = fmaxf(a10 + b0, 0.f); out[r1 * N + c1] = fmaxf(a11 + b1, 0.f); }
    } else {
        if (r0 < M) { out[r0 * N + c0] += a00 + b0; out[r0 * N + c1] += a01 + b1; }
        if (r1 < M) { out[r1 * N + c0] += a10 + b0; out[r1 * N + c1] += a11 + b1; }
    }
}

// ---------------- aggregation: out[d,c] = mean_h sum_s alpha*xl + bias ------
// grid (8 c-tiles, 11 d-tiles, B). Block: 16 d x 32 c, thread = 1d x 2c.
__global__ __launch_bounds__(256) void agg_kernel(const float* __restrict__ alpha,
                                                  const float* __restrict__ xl,
                                                  const float* __restrict__ bias_l,
                                                  float* __restrict__ out)
{
    __shared__ float Asm[16][33];
    __shared__ __align__(16) float Xs[32][34];
    int tid = threadIdx.x;
    int tx = tid & 15, ty = tid >> 4;
    int c0 = blockIdx.x * 32;
    int d0 = blockIdx.y * 16;
    int b = blockIdx.z;
    int d = d0 + ty;
    bool dok = d < N_;
    float accx = 0.f, accy = 0.f;

    for (int h = 0; h < H_; h++) {
        const float* arow = alpha + (size_t)(b * H_ + h) * N_ * N_;
        for (int sk = 0; sk < 192; sk += 32) {
            {
                int s_a = sk + tx * 2;
                float v0 = (dok && s_a < N_)     ? arow[(size_t)d * N_ + s_a]     : 0.f;
                float v1 = (dok && s_a + 1 < N_) ? arow[(size_t)d * N_ + s_a + 1] : 0.f;
                Asm[ty][tx * 2] = v0;
                Asm[ty][tx * 2 + 1] = v1;
            }
#pragma unroll
            for (int i = 0; i < 2; i++) {
                int f = tid + 256 * i;
                int row = f >> 4, cc = (f & 15) * 2;
                int s = sk + row;
                float2 v = make_float2(0.f, 0.f);
                if (s < N_) v = *(const float2*)&xl[(size_t)(b * N_ + s) * HC_ + h * C_ + c0 + cc];
                *(float2*)&Xs[row][cc] = v;
            }
            __syncthreads();
#pragma unroll
            for (int k = 0; k < 32; k++) {
                float av = Asm[ty][k];
                float2 x2 = *(const float2*)&Xs[k][tx * 2];
                accx = fmaf(av, x2.x, accx);
                accy = fmaf(av, x2.y, accy);
            }
            __syncthreads();
        }
    }

    if (dok) {
        int c = c0 + tx * 2;
        out[(size_t)(b * N_ + d) * C_ + c]     = 0.25f * accx + bias_l[c];
        out[(size_t)(b * N_ + d) * C_ + c + 1] = 0.25f * accy + bias_l[c + 1];
    }
}

// ---------------- layernorm over C=256 per node ------------------------------
__global__ void ln_kernel(const float* __restrict__ in,
                          const float* __restrict__ g,
                          const float* __restrict__ bt,
                          float* __restrict__ out)
{
    int row = blockIdx.x, t = threadIdx.x;
    int lane = t & 31, w = t >> 5;
    float v = in[row * C_ + t];

    __shared__ float red[8];
    __shared__ float stat;

    float s = v;
#pragma unroll
    for (int o = 16; o; o >>= 1) s += __shfl_xor_sync(0xffffffffu, s, o);
    if (lane == 0) red[w] = s;
    __syncthreads();
    if (t == 0) {
        float tot = 0.f;
#pragma unroll
        for (int i = 0; i < 8; i++) tot += red[i];
        stat = tot * (1.f / C_);
    }
    __syncthreads();
    float mu = stat;
    float dd = v - mu;
    float s2 = dd * dd;
#pragma unroll
    for (int o = 16; o; o >>= 1) s2 += __shfl_xor_sync(0xffffffffu, s2, o);
    __syncthreads();
    if (lane == 0) red[w] = s2;
    __syncthreads();
    if (t == 0) {
        float tot = 0.f;
#pragma unroll
        for (int i = 0; i < 8; i++) tot += red[i];
        stat = rsqrtf(tot * (1.f / C_) + 1e-5f);
    }
    __syncthreads();
    out[row * C_ + t] = dd * stat * g[t] + bt[t];
}

// ---------------- final mean pool per graph ----------------------------------
__global__ void pool_kernel(const float* __restrict__ x, float* __restrict__ out)
{
    int b = blockIdx.x, t = threadIdx.x;
    float s = 0.f;
#pragma unroll 13
    for (int d = 0; d < N_; d++) s += x[(b * N_ + d) * C_ + t];
    out[b * C_ + t] = s * (1.f / N_);
}

__global__ void copy_kernel(const float* __restrict__ src, float* __restrict__ dst)
{
    int i = blockIdx.x * 256 + threadIdx.x;
    dst[i] = src[i];
}

// ---------------- host launcher -----------------------------------------------
extern "C" void kernel_launch(void* const* d_in, const int* in_sizes, int n_in,
                              void* d_out, int out_size)
{
    const float* x    = (const float*)d_in[0];
    const float* Wl   = (const float*)d_in[1];
    const float* bl   = (const float*)d_in[2];
    const float* Wr   = (const float*)d_in[3];
    const float* br   = (const float*)d_in[4];
    const float* att  = (const float*)d_in[5];
    const float* bias = (const float*)d_in[6];
    const float* lng  = (const float*)d_in[7];
    const float* lnb  = (const float*)d_in[8];
    const float* W1   = (const float*)d_in[9];
    const float* b1   = (const float*)d_in[10];
    const float* W2   = (const float*)d_in[11];
    const float* b2   = (const float*)d_in[12];

    float *bx, *bxl, *bxr, *bal, *bhp, *bh, *bm;
    cudaGetSymbolAddress((void**)&bx,  g_x);
    cudaGetSymbolAddress((void**)&bxl, g_xl);
    cudaGetSymbolAddress((void**)&bxr, g_xr);
    cudaGetSymbolAddress((void**)&bal, g_alpha);
    cudaGetSymbolAddress((void**)&bhp, g_hpre);
    cudaGetSymbolAddress((void**)&bh,  g_h);
    cudaGetSymbolAddress((void**)&bm,  g_m);

    copy_kernel<<<NN_, 256>>>(x, bx);

    for (int l = 0; l < L_; l++) {
        gemm_dual<<<dim3(64, 6), 256>>>(bx,
                                        Wl + l * C_ * HC_, bl + l * HC_, bxl,
                                        Wr + l * C_ * HC_, br + l * HC_, bxr,
                                        NN_, C_);
        attn_kernel<<<dim3(11, 8), 256>>>(bxl, bxr, att + l * H_ * C_, bal);
        agg_kernel<<<dim3(8, 11, 2), 256>>>(bal, bxl, bias + l * C_, bhp);
        ln_kernel<<<NN_, 256>>>(bhp, lng + l * C_, lnb + l * C_, bh);
        gemm_kernel<<<dim3(16, 11), 256>>>(bh, W1 + l * C_ * 2 * C_, b1 + l * 2 * C_,
                                           bm, NN_, 2 * C_, C_, 1);
        gemm_kernel<<<dim3(8, 11), 256>>>(bm, W2 + l * 2 * C_ * C_, b2 + l * C_,
                                          bx, NN_, C_, 2 * C_, 2);
    }

    pool_kernel<<<B_, 256>>>(bx, (float*)d_out);
}

// round 3
// speedup vs baseline: 1.2304x; 1.1188x over previous
#include <cuda_runtime.h>

#define B_   2
#define N_   169
#define NN_  338
#define C_   256
#define H_   4
#define HC_  1024
#define L_   3

typedef unsigned long long ull;

// ---------------- scratch (device globals) ---------------------------------
__device__ float g_x[NN_ * C_];               // running node features
__device__ float g_xl[NN_ * HC_];             // x @ Wl + bl
__device__ float g_xr[NN_ * HC_];             // x @ Wr + br
__device__ float g_agg[B_ * H_ * N_ * C_];    // per-head aggregation partials
__device__ float g_h[NN_ * C_];               // post layernorm
__device__ float g_m[NN_ * 2 * C_];           // mlp hidden

// ---------------- packed f32x2 MAC for leaky-relu attention ----------------
__device__ __forceinline__ void mac2(ull l, ull r, ull a6, ull a4, ull msk, ull& acc)
{
    ull s, m;
    asm("add.rn.f32x2 %0, %1, %2;" : "=l"(s) : "l"(l), "l"(r));
    asm("and.b64 %0, %1, %2;"      : "=l"(m) : "l"(s), "l"(msk));
    asm("fma.rn.f32x2 %0, %1, %2, %0;" : "+l"(acc) : "l"(s), "l"(a6));
    asm("fma.rn.f32x2 %0, %1, %2, %0;" : "+l"(acc) : "l"(m), "l"(a4));
}

// ---------------- fused logits + softmax + aggregation ----------------------
// grid (22 d-tiles, 8 bh), block 256 = 8 d-rows x 32 lanes.
// Phase A: logit(d,s) = sum_c lrelu(xl[s,c]+xr[d,c])*att[c]; row softmax.
// Phase B: agg[bh,d,c] = sum_s alpha(d,s) * xl[s,h,c]   (per-head partial)
__global__ __launch_bounds__(256) void attn_agg_kernel(const float* __restrict__ xl,
                                                       const float* __restrict__ xr,
                                                       const float* __restrict__ att_l,
                                                       float* __restrict__ agg)
{
    __shared__ __align__(16) union {
        struct {
            float XR[8][40];
            float XLs[6][32][38];
            float A6[32];
            float A4[32];
        } pa;
        struct {
            float Xs[32][260];
        } pb;
    } u;
    __shared__ float AL[8][193];

    int tid = threadIdx.x;
    int lane = tid & 31, ty = tid >> 5;
    int dt = blockIdx.x, bh = blockIdx.y;
    int b = bh >> 2, h = bh & 3;
    int d = dt * 8 + ty;
    bool dok = d < N_;

    ull acc[6];
#pragma unroll
    for (int st = 0; st < 6; st++) acc[st] = 0ull;
    const ull msk = 0x7FFFFFFF7FFFFFFFULL;

    // ---------------- Phase A: logits ----------------
    for (int ck = 0; ck < C_; ck += 32) {
        u.pa.XR[ty][lane] = dok ? xr[(size_t)(b * N_ + d) * HC_ + h * C_ + ck + lane] : 0.f;
        if (tid < 32) {
            float a = att_l[h * C_ + ck + tid];
            u.pa.A6[tid] = 0.6f * a;
            u.pa.A4[tid] = 0.4f * a;
        }
#pragma unroll
        for (int i = 0; i < 12; i++) {
            int f = tid + 256 * i;          // 3072 float2 total
            int st = f >> 9;                // 512 float2 per st-band
            int rem = f & 511;
            int row = rem >> 4;
            int cc = (rem & 15) * 2;
            int s = st * 32 + row;
            float2 v = make_float2(0.f, 0.f);
            if (s < N_) v = *(const float2*)&xl[(size_t)(b * N_ + s) * HC_ + h * C_ + ck + cc];
            *(float2*)&u.pa.XLs[st][row][cc] = v;
        }
        __syncthreads();
#pragma unroll
        for (int c2 = 0; c2 < 16; c2++) {
            ull r  = *(const ull*)&u.pa.XR[ty][c2 * 2];
            ull a6 = *(const ull*)&u.pa.A6[c2 * 2];
            ull a4 = *(const ull*)&u.pa.A4[c2 * 2];
#pragma unroll
            for (int st = 0; st < 6; st++) {
                ull l = *(const ull*)&u.pa.XLs[st][lane][c2 * 2];
                mac2(l, r, a6, a4, msk, acc[st]);
            }
        }
        __syncthreads();
    }

    // ---------------- softmax over s (one warp per d-row) ----------------
    float lg[6];
    float mx = -1e30f;
#pragma unroll
    for (int st = 0; st < 6; st++) {
        ull a = acc[st];
        float lo = __uint_as_float((unsigned)(a & 0xffffffffu));
        float hi = __uint_as_float((unsigned)(a >> 32));
        float v = lo + hi;
        int s = st * 32 + lane;
        if (s >= N_ || s == d) v = -1e30f;
        lg[st] = v;
        mx = fmaxf(mx, v);
    }
#pragma unroll
    for (int o = 16; o; o >>= 1) mx = fmaxf(mx, __shfl_xor_sync(0xffffffffu, mx, o));
    float sum = 0.f;
#pragma unroll
    for (int st = 0; st < 6; st++) {
        float e = __expf(lg[st] - mx);
        lg[st] = e;
        sum += e;
    }
#pragma unroll
    for (int o = 16; o; o >>= 1) sum += __shfl_xor_sync(0xffffffffu, sum, o);
    float inv = 1.f / (sum + 1e-16f);
#pragma unroll
    for (int st = 0; st < 6; st++) AL[ty][st * 32 + lane] = lg[st] * inv;   // zeros for s>=169
    __syncthreads();

    // ---------------- Phase B: agg GEMM 8d x 256c x 192s ----------------
    float4 acc0 = make_float4(0.f, 0.f, 0.f, 0.f);
    float4 acc1 = make_float4(0.f, 0.f, 0.f, 0.f);
    for (int sk = 0; sk < 192; sk += 32) {
#pragma unroll
        for (int i = 0; i < 8; i++) {
            int f = tid + 256 * i;          // 2048 float4 total
            int row = f >> 6, col4 = f & 63;
            int s = sk + row;
            float4 v = make_float4(0.f, 0.f, 0.f, 0.f);
            if (s < N_) v = *(const float4*)&xl[(size_t)(b * N_ + s) * HC_ + h * C_ + col4 * 4];
            *(float4*)&u.pb.Xs[row][col4 * 4] = v;
        }
        __syncthreads();
#pragma unroll
        for (int k = 0; k < 32; k++) {
            float av = AL[ty][sk + k];
            float4 x0 = *(const float4*)&u.pb.Xs[k][lane * 4];
            float4 x1 = *(const float4*)&u.pb.Xs[k][lane * 4 + 128];
            acc0.x = fmaf(av, x0.x, acc0.x); acc0.y = fmaf(av, x0.y, acc0.y);
            acc0.z = fmaf(av, x0.z, acc0.z); acc0.w = fmaf(av, x0.w, acc0.w);
            acc1.x = fmaf(av, x1.x, acc1.x); acc1.y = fmaf(av, x1.y, acc1.y);
            acc1.z = fmaf(av, x1.z, acc1.z); acc1.w = fmaf(av, x1.w, acc1.w);
        }
        __syncthreads();
    }

    if (dok) {
        float* o = agg + ((size_t)bh * N_ + d) * C_;
        *(float4*)&o[lane * 4]       = acc0;
        *(float4*)&o[lane * 4 + 128] = acc1;
    }
}

// ---------------- fused xl/xr GEMM: 64x32 tile, 4x2 per thread --------------
__global__ __launch_bounds__(256) void gemm_dual(const float* __restrict__ A,
                                                 const float* __restrict__ B1,
                                                 const float* __restrict__ c1,
                                                 float* __restrict__ o1,
                                                 const float* __restrict__ B2,
                                                 const float* __restrict__ c2p,
                                                 float* __restrict__ o2,
                                                 int M, int K)
{
    __shared__ __align__(16) float As[16][68];
    __shared__ __align__(16) float Bs[16][34];

    const float* Bm;
    const float* bias;
    float* out;
    int n0;
    if (blockIdx.x < 32) { Bm = B1; bias = c1;  out = o1; n0 = blockIdx.x * 32; }
    else                 { Bm = B2; bias = c2p; out = o2; n0 = (blockIdx.x - 32) * 32; }

    int tid = threadIdx.x;
    int tx = tid & 15, ty = tid >> 4;
    int m0 = blockIdx.y * 64;
    int lm = tid & 63, kq = tid >> 6;
    int bk = tid >> 4, bn = (tid & 15) * 2;

    float acc[4][2];
#pragma unroll
    for (int i = 0; i < 4; i++) { acc[i][0] = 0.f; acc[i][1] = 0.f; }

    for (int kk = 0; kk < K; kk += 16) {
        float4 f = make_float4(0.f, 0.f, 0.f, 0.f);
        if (m0 + lm < M) f = *(const float4*)&A[(size_t)(m0 + lm) * K + kk + kq * 4];
        As[kq * 4 + 0][lm] = f.x;
        As[kq * 4 + 1][lm] = f.y;
        As[kq * 4 + 2][lm] = f.z;
        As[kq * 4 + 3][lm] = f.w;
        *(float2*)&Bs[bk][bn] = *(const float2*)&Bm[(size_t)(kk + bk) * HC_ + n0 + bn];
        __syncthreads();
#pragma unroll
        for (int k = 0; k < 16; k++) {
            float4 a = *(const float4*)&As[k][ty * 4];
            float2 bv = *(const float2*)&Bs[k][tx * 2];
            acc[0][0] = fmaf(a.x, bv.x, acc[0][0]); acc[0][1] = fmaf(a.x, bv.y, acc[0][1]);
            acc[1][0] = fmaf(a.y, bv.x, acc[1][0]); acc[1][1] = fmaf(a.y, bv.y, acc[1][1]);
            acc[2][0] = fmaf(a.z, bv.x, acc[2][0]); acc[2][1] = fmaf(a.z, bv.y, acc[2][1]);
            acc[3][0] = fmaf(a.w, bv.x, acc[3][0]); acc[3][1] = fmaf(a.w, bv.y, acc[3][1]);
        }
        __syncthreads();
    }

    float b0 = bias[n0 + tx * 2], b1 = bias[n0 + tx * 2 + 1];
#pragma unroll
    for (int i = 0; i < 4; i++) {
        int r = m0 + ty * 4 + i;
        if (r < M) {
            out[(size_t)r * HC_ + n0 + tx * 2]     = acc[i][0] + b0;
            out[(size_t)r * HC_ + n0 + tx * 2 + 1] = acc[i][1] + b1;
        }
    }
}

// ---------------- generic 32x32 tiled fp32 GEMM (MLP path) ------------------
// mode: 0 plain, 1 relu, 2 residual +=
__global__ void gemm_kernel(const float* __restrict__ A,
                            const float* __restrict__ Bm,
                            const float* __restrict__ bias,
                            float* __restrict__ out,
                            int M, int N, int K, int mode)
{
    __shared__ float As[32][33];
    __shared__ float Bs[32][33];
    int tid = threadIdx.x;
    int tx = tid & 15, ty = tid >> 4;
    int m0 = blockIdx.y * 32;
    int n0 = blockIdx.x * 32;
    float a00 = 0.f, a01 = 0.f, a10 = 0.f, a11 = 0.f;

    for (int kk = 0; kk < K; kk += 32) {
#pragma unroll
        for (int i = 0; i < 4; i++) {
            int ii = tid + i * 256;
            int r = ii >> 5, c = ii & 31;
            int arow = m0 + r;
            As[r][c] = (arow < M) ? A[arow * K + kk + c] : 0.f;
            Bs[r][c] = Bm[(kk + r) * N + n0 + c];
        }
        __syncthreads();
#pragma unroll
        for (int k = 0; k < 32; k++) {
            float av0 = As[ty][k],      av1 = As[ty + 16][k];
            float bv0 = Bs[k][tx],      bv1 = Bs[k][tx + 16];
            a00 = fmaf(av0, bv0, a00);  a01 = fmaf(av0, bv1, a01);
            a10 = fmaf(av1, bv0, a10);  a11 = fmaf(av1, bv1, a11);
        }
        __syncthreads();
    }

    int r0 = m0 + ty, r1 = m0 + ty + 16;
    int c0 = n0 + tx, c1 = n0 + tx + 16;
    float b0 = bias[c0], b1 = bias[c1];
    if (mode == 0) {
        if (r0 < M) { out[r0 * N + c0] = a00 + b0; out[r0 * N + c1] = a01 + b1; }
        if (r1 < M) { out[r1 * N + c0] = a10 + b0; out[r1 * N + c1] = a11 + b1; }
    } else if (mode == 1) {
        if (r0 < M) { out[r0 * N + c0] = fmaxf(a00 + b0, 0.f); out[r0 * N + c1] = fmaxf(a01 + b1, 0.f); }
        if (r1 < M) { out[r1 * N + c0] = fmaxf(a10 + b0, 0.f); out[r1 * N + c1] = fmaxf(a11 + b1, 0.f); }
    } else {
        if (r0 < M) { out[r0 * N + c0] += a00 + b0; out[r0 * N + c1] += a01 + b1; }
        if (r1 < M) { out[r1 * N + c0] += a10 + b0; out[r1 * N + c1] += a11 + b1; }
    }
}

// ---------------- head-mean + bias + layernorm -------------------------------
__global__ void ln_kernel(const float* __restrict__ agg,
                          const float* __restrict__ bias_l,
                          const float* __restrict__ g,
                          const float* __restrict__ bt,
                          float* __restrict__ out)
{
    int n = blockIdx.x, t = threadIdx.x;
    int lane = t & 31, w = t >> 5;
    int b = (n >= N_) ? 1 : 0;
    int d = n - b * N_;

    float v = 0.f;
#pragma unroll
    for (int h = 0; h < H_; h++)
        v += agg[((size_t)(b * H_ + h) * N_ + d) * C_ + t];
    v = 0.25f * v + bias_l[t];

    __shared__ float red[8];
    __shared__ float stat;

    float s = v;
#pragma unroll
    for (int o = 16; o; o >>= 1) s += __shfl_xor_sync(0xffffffffu, s, o);
    if (lane == 0) red[w] = s;
    __syncthreads();
    if (t == 0) {
        float tot = 0.f;
#pragma unroll
        for (int i = 0; i < 8; i++) tot += red[i];
        stat = tot * (1.f / C_);
    }
    __syncthreads();
    float mu = stat;
    float dd = v - mu;
    float s2 = dd * dd;
#pragma unroll
    for (int o = 16; o; o >>= 1) s2 += __shfl_xor_sync(0xffffffffu, s2, o);
    __syncthreads();
    if (lane == 0) red[w] = s2;
    __syncthreads();
    if (t == 0) {
        float tot = 0.f;
#pragma unroll
        for (int i = 0; i < 8; i++) tot += red[i];
        stat = rsqrtf(tot * (1.f / C_) + 1e-5f);
    }
    __syncthreads();
    out[n * C_ + t] = dd * stat * g[t] + bt[t];
}

// ---------------- final mean pool per graph ----------------------------------
__global__ void pool_kernel(const float* __restrict__ x, float* __restrict__ out)
{
    int b = blockIdx.x, t = threadIdx.x;
    float s = 0.f;
#pragma unroll 13
    for (int d = 0; d < N_; d++) s += x[(b * N_ + d) * C_ + t];
    out[b * C_ + t] = s * (1.f / N_);
}

__global__ void copy_kernel(const float* __restrict__ src, float* __restrict__ dst)
{
    int i = blockIdx.x * 256 + threadIdx.x;
    dst[i] = src[i];
}

// ---------------- host launcher -----------------------------------------------
extern "C" void kernel_launch(void* const* d_in, const int* in_sizes, int n_in,
                              void* d_out, int out_size)
{
    const float* x    = (const float*)d_in[0];
    const float* Wl   = (const float*)d_in[1];
    const float* bl   = (const float*)d_in[2];
    const float* Wr   = (const float*)d_in[3];
    const float* br   = (const float*)d_in[4];
    const float* att  = (const float*)d_in[5];
    const float* bias = (const float*)d_in[6];
    const float* lng  = (const float*)d_in[7];
    const float* lnb  = (const float*)d_in[8];
    const float* W1   = (const float*)d_in[9];
    const float* b1   = (const float*)d_in[10];
    const float* W2   = (const float*)d_in[11];
    const float* b2   = (const float*)d_in[12];

    float *bx, *bxl, *bxr, *bag, *bh, *bm;
    cudaGetSymbolAddress((void**)&bx,  g_x);
    cudaGetSymbolAddress((void**)&bxl, g_xl);
    cudaGetSymbolAddress((void**)&bxr, g_xr);
    cudaGetSymbolAddress((void**)&bag, g_agg);
    cudaGetSymbolAddress((void**)&bh,  g_h);
    cudaGetSymbolAddress((void**)&bm,  g_m);

    copy_kernel<<<NN_, 256>>>(x, bx);

    for (int l = 0; l < L_; l++) {
        gemm_dual<<<dim3(64, 6), 256>>>(bx,
                                        Wl + l * C_ * HC_, bl + l * HC_, bxl,
                                        Wr + l * C_ * HC_, br + l * HC_, bxr,
                                        NN_, C_);
        attn_agg_kernel<<<dim3(22, 8), 256>>>(bxl, bxr, att + l * H_ * C_, bag);
        ln_kernel<<<NN_, 256>>>(bag, bias + l * C_, lng + l * C_, lnb + l * C_, bh);
        gemm_kernel<<<dim3(16, 11), 256>>>(bh, W1 + l * C_ * 2 * C_, b1 + l * 2 * C_,
                                           bm, NN_, 2 * C_, C_, 1);
        gemm_kernel<<<dim3(8, 11), 256>>>(bm, W2 + l * 2 * C_ * C_, b2 + l * C_,
                                          bx, NN_, C_, 2 * C_, 2);
    }

    pool_kernel<<<B_, 256>>>(bx, (float*)d_out);
}

// round 4
// speedup vs baseline: 1.2887x; 1.0474x over previous
#include <cuda_runtime.h>

#define B_   2
#define N_   169
#define NN_  338
#define C_   256
#define H_   4
#define HC_  1024
#define L_   3

typedef unsigned long long ull;

// ---------------- scratch (device globals) ---------------------------------
__device__ float g_x[NN_ * C_];               // running node features
__device__ float g_xl[NN_ * HC_];             // x @ Wl + bl
__device__ float g_xr[NN_ * HC_];             // x @ Wr + br
__device__ float g_agg[B_ * H_ * N_ * C_];    // per-head aggregation partials
__device__ float g_h[NN_ * C_];               // post layernorm
__device__ float g_m[NN_ * 2 * C_];           // mlp hidden
__device__ float g_u[H_ * NN_];               // <att, xl_n> per head
__device__ float g_w[H_ * NN_];               // <att, xr_n> per head

// ---------------- u/w rank-1 terms: u[h,n]=<att_h, xl[n,h,:]>, w likewise ---
__global__ __launch_bounds__(128) void uw_kernel(const float* __restrict__ xl,
                                                 const float* __restrict__ xr,
                                                 const float* __restrict__ att_l,
                                                 float* __restrict__ u,
                                                 float* __restrict__ w)
{
    int n = blockIdx.x;
    int h = threadIdx.x >> 5, lane = threadIdx.x & 31;
    const float4* xlp = (const float4*)&xl[(size_t)n * HC_ + h * C_];
    const float4* xrp = (const float4*)&xr[(size_t)n * HC_ + h * C_];
    const float4* ap  = (const float4*)&att_l[h * C_];
    float su = 0.f, sw = 0.f;
#pragma unroll
    for (int i = 0; i < 2; i++) {
        float4 a = ap[lane + 32 * i];
        float4 vl = xlp[lane + 32 * i];
        float4 vr = xrp[lane + 32 * i];
        su += a.x * vl.x + a.y * vl.y + a.z * vl.z + a.w * vl.w;
        sw += a.x * vr.x + a.y * vr.y + a.z * vr.z + a.w * vr.w;
    }
#pragma unroll
    for (int o = 16; o; o >>= 1) {
        su += __shfl_xor_sync(0xffffffffu, su, o);
        sw += __shfl_xor_sync(0xffffffffu, sw, o);
    }
    if (lane == 0) {
        u[h * NN_ + n] = su;
        w[h * NN_ + n] = sw;
    }
}

// ---------------- fused logits + softmax + aggregation ----------------------
// grid (22 d-tiles, 8 bh), block 256 = 8 d-rows x 32 lanes.
// logit(d,s) = 0.6*(u_s + w_d) + 0.4 * sum_c att_c * |xl[s,c]+xr[d,c]|
__global__ __launch_bounds__(256) void attn_agg_kernel(const float* __restrict__ xl,
                                                       const float* __restrict__ xr,
                                                       const float* __restrict__ att_l,
                                                       const float* __restrict__ u,
                                                       const float* __restrict__ w,
                                                       float* __restrict__ agg)
{
    __shared__ __align__(16) union {
        struct {
            float XR[8][40];
            float XLs[6][32][38];
            float A4[32];
        } pa;
        struct {
            float Xs[32][260];
        } pb;
    } un;
    __shared__ float AL[8][193];

    int tid = threadIdx.x;
    int lane = tid & 31, ty = tid >> 5;
    int dt = blockIdx.x, bh = blockIdx.y;
    int b = bh >> 2, h = bh & 3;
    int d = dt * 8 + ty;
    bool dok = d < N_;

    ull acc[6];
#pragma unroll
    for (int st = 0; st < 6; st++) acc[st] = 0ull;
    const ull msk = 0x7FFFFFFF7FFFFFFFULL;

    // ---------------- Phase A: |.| part of logits ----------------
    for (int ck = 0; ck < C_; ck += 32) {
        un.pa.XR[ty][lane] = dok ? xr[(size_t)(b * N_ + d) * HC_ + h * C_ + ck + lane] : 0.f;
        if (tid < 32) un.pa.A4[tid] = 0.4f * att_l[h * C_ + ck + tid];
#pragma unroll
        for (int i = 0; i < 12; i++) {
            int f = tid + 256 * i;          // 3072 float2 total
            int st = f >> 9;
            int rem = f & 511;
            int row = rem >> 4;
            int cc = (rem & 15) * 2;
            int s = st * 32 + row;
            float2 v = make_float2(0.f, 0.f);
            if (s < N_) v = *(const float2*)&xl[(size_t)(b * N_ + s) * HC_ + h * C_ + ck + cc];
            *(float2*)&un.pa.XLs[st][row][cc] = v;
        }
        __syncthreads();
#pragma unroll
        for (int c2 = 0; c2 < 16; c2++) {
            ull r  = *(const ull*)&un.pa.XR[ty][c2 * 2];
            ull a4 = *(const ull*)&un.pa.A4[c2 * 2];
#pragma unroll
            for (int st = 0; st < 6; st++) {
                ull l = *(const ull*)&un.pa.XLs[st][lane][c2 * 2];
                ull s, m;
                asm("add.rn.f32x2 %0, %1, %2;" : "=l"(s) : "l"(l), "l"(r));
                asm("and.b64 %0, %1, %2;"      : "=l"(m) : "l"(s), "l"(msk));
                asm("fma.rn.f32x2 %0, %1, %2, %0;" : "+l"(acc[st]) : "l"(m), "l"(a4));
            }
        }
        __syncthreads();
    }

    // ---------------- softmax over s (one warp per d-row) ----------------
    float w_d = dok ? w[h * NN_ + b * N_ + d] : 0.f;
    float lg[6];
    float mx = -1e30f;
#pragma unroll
    for (int st = 0; st < 6; st++) {
        ull a = acc[st];
        float lo = __uint_as_float((unsigned)(a & 0xffffffffu));
        float hi = __uint_as_float((unsigned)(a >> 32));
        int s = st * 32 + lane;
        float uv = (s < N_) ? u[h * NN_ + b * N_ + s] : 0.f;
        float v = 0.6f * (uv + w_d) + lo + hi;
        if (s >= N_ || s == d) v = -1e30f;
        lg[st] = v;
        mx = fmaxf(mx, v);
    }
#pragma unroll
    for (int o = 16; o; o >>= 1) mx = fmaxf(mx, __shfl_xor_sync(0xffffffffu, mx, o));
    float sum = 0.f;
#pragma unroll
    for (int st = 0; st < 6; st++) {
        float e = __expf(lg[st] - mx);
        lg[st] = e;
        sum += e;
    }
#pragma unroll
    for (int o = 16; o; o >>= 1) sum += __shfl_xor_sync(0xffffffffu, sum, o);
    float inv = 1.f / (sum + 1e-16f);
#pragma unroll
    for (int st = 0; st < 6; st++) AL[ty][st * 32 + lane] = lg[st] * inv;   // zeros for s>=169
    __syncthreads();

    // ---------------- Phase B: agg GEMM 8d x 256c x 192s ----------------
    float4 acc0 = make_float4(0.f, 0.f, 0.f, 0.f);
    float4 acc1 = make_float4(0.f, 0.f, 0.f, 0.f);
    for (int sk = 0; sk < 192; sk += 32) {
#pragma unroll
        for (int i = 0; i < 8; i++) {
            int f = tid + 256 * i;          // 2048 float4 total
            int row = f >> 6, col4 = f & 63;
            int s = sk + row;
            float4 v = make_float4(0.f, 0.f, 0.f, 0.f);
            if (s < N_) v = *(const float4*)&xl[(size_t)(b * N_ + s) * HC_ + h * C_ + col4 * 4];
            *(float4*)&un.pb.Xs[row][col4 * 4] = v;
        }
        __syncthreads();
#pragma unroll
        for (int k = 0; k < 32; k++) {
            float av = AL[ty][sk + k];
            float4 x0 = *(const float4*)&un.pb.Xs[k][lane * 4];
            float4 x1 = *(const float4*)&un.pb.Xs[k][lane * 4 + 128];
            acc0.x = fmaf(av, x0.x, acc0.x); acc0.y = fmaf(av, x0.y, acc0.y);
            acc0.z = fmaf(av, x0.z, acc0.z); acc0.w = fmaf(av, x0.w, acc0.w);
            acc1.x = fmaf(av, x1.x, acc1.x); acc1.y = fmaf(av, x1.y, acc1.y);
            acc1.z = fmaf(av, x1.z, acc1.z); acc1.w = fmaf(av, x1.w, acc1.w);
        }
        __syncthreads();
    }

    if (dok) {
        float* o = agg + ((size_t)bh * N_ + d) * C_;
        *(float4*)&o[lane * 4]       = acc0;
        *(float4*)&o[lane * 4 + 128] = acc1;
    }
}

// ---------------- fused xl/xr GEMM: 64x32 tile, kk=32, 4x2 per thread -------
__global__ __launch_bounds__(256) void gemm_dual(const float* __restrict__ A,
                                                 const float* __restrict__ B1,
                                                 const float* __restrict__ c1,
                                                 float* __restrict__ o1,
                                                 const float* __restrict__ B2,
                                                 const float* __restrict__ c2p,
                                                 float* __restrict__ o2,
                                                 int M, int K)
{
    __shared__ __align__(16) float As[32][68];
    __shared__ __align__(16) float Bs[32][33];

    const float* Bm;
    const float* bias;
    float* out;
    int n0;
    if (blockIdx.x < 32) { Bm = B1; bias = c1;  out = o1; n0 = blockIdx.x * 32; }
    else                 { Bm = B2; bias = c2p; out = o2; n0 = (blockIdx.x - 32) * 32; }

    int tid = threadIdx.x;
    int tx = tid & 15, ty = tid >> 4;
    int m0 = blockIdx.y * 64;
    int lm = tid & 63, kq = tid >> 6;       // A: row lm, k-quads kq & kq+4
    int br = tid >> 3, bc = (tid & 7) * 4;  // B: row br, col4 bc

    float acc[4][2];
#pragma unroll
    for (int i = 0; i < 4; i++) { acc[i][0] = 0.f; acc[i][1] = 0.f; }

    for (int kk = 0; kk < K; kk += 32) {
#pragma unroll
        for (int q = 0; q < 2; q++) {
            int kb = (kq + q * 4) * 4;
            float4 f = make_float4(0.f, 0.f, 0.f, 0.f);
            if (m0 + lm < M) f = *(const float4*)&A[(size_t)(m0 + lm) * K + kk + kb];
            As[kb + 0][lm] = f.x;
            As[kb + 1][lm] = f.y;
            As[kb + 2][lm] = f.z;
            As[kb + 3][lm] = f.w;
        }
        {
            float4 f = *(const float4*)&Bm[(size_t)(kk + br) * HC_ + n0 + bc];
            Bs[br][bc + 0] = f.x;
            Bs[br][bc + 1] = f.y;
            Bs[br][bc + 2] = f.z;
            Bs[br][bc + 3] = f.w;
        }
        __syncthreads();
#pragma unroll
        for (int k = 0; k < 32; k++) {
            float4 a = *(const float4*)&As[k][ty * 4];
            float bv0 = Bs[k][tx * 2], bv1 = Bs[k][tx * 2 + 1];
            acc[0][0] = fmaf(a.x, bv0, acc[0][0]); acc[0][1] = fmaf(a.x, bv1, acc[0][1]);
            acc[1][0] = fmaf(a.y, bv0, acc[1][0]); acc[1][1] = fmaf(a.y, bv1, acc[1][1]);
            acc[2][0] = fmaf(a.z, bv0, acc[2][0]); acc[2][1] = fmaf(a.z, bv1, acc[2][1]);
            acc[3][0] = fmaf(a.w, bv0, acc[3][0]); acc[3][1] = fmaf(a.w, bv1, acc[3][1]);
        }
        __syncthreads();
    }

    float b0 = bias[n0 + tx * 2], b1 = bias[n0 + tx * 2 + 1];
#pragma unroll
    for (int i = 0; i < 4; i++) {
        int r = m0 + ty * 4 + i;
        if (r < M) {
            out[(size_t)r * HC_ + n0 + tx * 2]     = acc[i][0] + b0;
            out[(size_t)r * HC_ + n0 + tx * 2 + 1] = acc[i][1] + b1;
        }
    }
}

// ---------------- generic 32x32 tiled fp32 GEMM (MLP path) ------------------
// mode: 1 relu, 2 residual +=
__global__ void gemm_kernel(const float* __restrict__ A,
                            const float* __restrict__ Bm,
                            const float* __restrict__ bias,
                            float* __restrict__ out,
                            int M, int N, int K, int mode)
{
    __shared__ float As[32][33];
    __shared__ float Bs[32][33];
    int tid = threadIdx.x;
    int tx = tid & 15, ty = tid >> 4;
    int m0 = blockIdx.y * 32;
    int n0 = blockIdx.x * 32;
    int lr = tid >> 3, lc = (tid & 7) * 4;
    float a00 = 0.f, a01 = 0.f, a10 = 0.f, a11 = 0.f;

    for (int kk = 0; kk < K; kk += 32) {
        {
            float4 f = make_float4(0.f, 0.f, 0.f, 0.f);
            if (m0 + lr < M) f = *(const float4*)&A[(size_t)(m0 + lr) * K + kk + lc];
            As[lr][lc + 0] = f.x; As[lr][lc + 1] = f.y;
            As[lr][lc + 2] = f.z; As[lr][lc + 3] = f.w;
            float4 g = *(const float4*)&Bm[(size_t)(kk + lr) * N + n0 + lc];
            Bs[lr][lc + 0] = g.x; Bs[lr][lc + 1] = g.y;
            Bs[lr][lc + 2] = g.z; Bs[lr][lc + 3] = g.w;
        }
        __syncthreads();
#pragma unroll
        for (int k = 0; k < 32; k++) {
            float av0 = As[ty][k],      av1 = As[ty + 16][k];
            float bv0 = Bs[k][tx],      bv1 = Bs[k][tx + 16];
            a00 = fmaf(av0, bv0, a00);  a01 = fmaf(av0, bv1, a01);
            a10 = fmaf(av1, bv0, a10);  a11 = fmaf(av1, bv1, a11);
        }
        __syncthreads();
    }

    int r0 = m0 + ty, r1 = m0 + ty + 16;
    int c0 = n0 + tx, c1 = n0 + tx + 16;
    float b0 = bias[c0], b1 = bias[c1];
    if (mode == 1) {
        if (r0 < M) { out[r0 * N + c0] = fmaxf(a00 + b0, 0.f); out[r0 * N + c1] = fmaxf(a01 + b1, 0.f); }
        if (r1 < M) { out[r1 * N + c0] = fmaxf(a10 + b0, 0.f); out[r1 * N + c1] = fmaxf(a11 + b1, 0.f); }
    } else {
        if (r0 < M) { out[r0 * N + c0] += a00 + b0; out[r0 * N + c1] += a01 + b1; }
        if (r1 < M) { out[r1 * N + c0] += a10 + b0; out[r1 * N + c1] += a11 + b1; }
    }
}

// ---------------- head-mean + bias + layernorm (4 rows/block, float4) -------
__global__ __launch_bounds__(256) void ln_kernel(const float* __restrict__ agg,
                                                 const float* __restrict__ bias_l,
                                                 const float* __restrict__ g,
                                                 const float* __restrict__ bt,
                                                 float* __restrict__ out)
{
    int ty = threadIdx.x >> 6;        // row in block 0..3
    int tx = threadIdx.x & 63;        // 64 threads x float4 = 256 c
    int wq = threadIdx.x >> 5;        // warp id 0..7
    int n = blockIdx.x * 4 + ty;
    bool ok = n < NN_;
    int b = (n >= N_) ? 1 : 0;
    int d = n - b * N_;

    float4 v = make_float4(0.f, 0.f, 0.f, 0.f);
    if (ok) {
#pragma unroll
        for (int h = 0; h < H_; h++) {
            float4 t = *(const float4*)&agg[((size_t)(b * H_ + h) * N_ + d) * C_ + tx * 4];
            v.x += t.x; v.y += t.y; v.z += t.z; v.w += t.w;
        }
        float4 bb = *(const float4*)&bias_l[tx * 4];
        v.x = 0.25f * v.x + bb.x; v.y = 0.25f * v.y + bb.y;
        v.z = 0.25f * v.z + bb.z; v.w = 0.25f * v.w + bb.w;
    }

    __shared__ float red[8];
    float s = v.x + v.y + v.z + v.w;
#pragma unroll
    for (int o = 16; o; o >>= 1) s += __shfl_xor_sync(0xffffffffu, s, o);
    if ((threadIdx.x & 31) == 0) red[wq] = s;
    __syncthreads();
    float mu = (red[ty * 2] + red[ty * 2 + 1]) * (1.f / C_);
    __syncthreads();

    float4 dd = make_float4(v.x - mu, v.y - mu, v.z - mu, v.w - mu);
    float s2 = dd.x * dd.x + dd.y * dd.y + dd.z * dd.z + dd.w * dd.w;
#pragma unroll
    for (int o = 16; o; o >>= 1) s2 += __shfl_xor_sync(0xffffffffu, s2, o);
    if ((threadIdx.x & 31) == 0) red[wq] = s2;
    __syncthreads();
    float rstd = rsqrtf((red[ty * 2] + red[ty * 2 + 1]) * (1.f / C_) + 1e-5f);

    if (ok) {
        float4 gg = *(const float4*)&g[tx * 4];
        float4 tb = *(const float4*)&bt[tx * 4];
        float4 o4;
        o4.x = dd.x * rstd * gg.x + tb.x;
        o4.y = dd.y * rstd * gg.y + tb.y;
        o4.z = dd.z * rstd * gg.z + tb.z;
        o4.w = dd.w * rstd * gg.w + tb.w;
        *(float4*)&out[(size_t)n * C_ + tx * 4] = o4;
    }
}

// ---------------- final mean pool per graph ----------------------------------
__global__ void pool_kernel(const float* __restrict__ x, float* __restrict__ out)
{
    int b = blockIdx.x, t = threadIdx.x;
    float s = 0.f;
#pragma unroll 13
    for (int d = 0; d < N_; d++) s += x[(b * N_ + d) * C_ + t];
    out[b * C_ + t] = s * (1.f / N_);
}

__global__ void copy_kernel(const float* __restrict__ src, float* __restrict__ dst)
{
    int i = blockIdx.x * 256 + threadIdx.x;
    dst[i] = src[i];
}

// ---------------- host launcher -----------------------------------------------
extern "C" void kernel_launch(void* const* d_in, const int* in_sizes, int n_in,
                              void* d_out, int out_size)
{
    const float* x    = (const float*)d_in[0];
    const float* Wl   = (const float*)d_in[1];
    const float* bl   = (const float*)d_in[2];
    const float* Wr   = (const float*)d_in[3];
    const float* br   = (const float*)d_in[4];
    const float* att  = (const float*)d_in[5];
    const float* bias = (const float*)d_in[6];
    const float* lng  = (const float*)d_in[7];
    const float* lnb  = (const float*)d_in[8];
    const float* W1   = (const float*)d_in[9];
    const float* b1   = (const float*)d_in[10];
    const float* W2   = (const float*)d_in[11];
    const float* b2   = (const float*)d_in[12];

    float *bx, *bxl, *bxr, *bag, *bh, *bm, *bu, *bw;
    cudaGetSymbolAddress((void**)&bx,  g_x);
    cudaGetSymbolAddress((void**)&bxl, g_xl);
    cudaGetSymbolAddress((void**)&bxr, g_xr);
    cudaGetSymbolAddress((void**)&bag, g_agg);
    cudaGetSymbolAddress((void**)&bh,  g_h);
    cudaGetSymbolAddress((void**)&bm,  g_m);
    cudaGetSymbolAddress((void**)&bu,  g_u);
    cudaGetSymbolAddress((void**)&bw,  g_w);

    copy_kernel<<<NN_, 256>>>(x, bx);

    for (int l = 0; l < L_; l++) {
        gemm_dual<<<dim3(64, 6), 256>>>(bx,
                                        Wl + l * C_ * HC_, bl + l * HC_, bxl,
                                        Wr + l * C_ * HC_, br + l * HC_, bxr,
                                        NN_, C_);
        uw_kernel<<<NN_, 128>>>(bxl, bxr, att + l * H_ * C_, bu, bw);
        attn_agg_kernel<<<dim3(22, 8), 256>>>(bxl, bxr, att + l * H_ * C_, bu, bw, bag);
        ln_kernel<<<85, 256>>>(bag, bias + l * C_, lng + l * C_, lnb + l * C_, bh);
        gemm_kernel<<<dim3(16, 11), 256>>>(bh, W1 + l * C_ * 2 * C_, b1 + l * 2 * C_,
                                           bm, NN_, 2 * C_, C_, 1);
        gemm_kernel<<<dim3(8, 11), 256>>>(bm, W2 + l * 2 * C_ * C_, b2 + l * C_,
                                          bx, NN_, C_, 2 * C_, 2);
    }

    pool_kernel<<<B_, 256>>>(bx, (float*)d_out);
}